// round 3
// baseline (speedup 1.0000x reference)
#include <cuda_runtime.h>
#include <cstdint>

// Attention: softmax(q@k^T/sqrt(8) + 1) with JAX threefry dropout(p=0.3, key 42), @ v
// B=256, H=32, S=16, D=64. One warp per head, 8 warps (8 heads) per block.
// Register-tiled, broadcast-coalesced global loads, no smem staging (P transpose only),
// f32x2 packed FMA.

#define ATT_SCALE 0.35355339059327373f  // 1/sqrt(8)

// ---------------- f32x2 helpers (Blackwell packed fp32) ----------------
__device__ __forceinline__ unsigned long long pk2(float lo, float hi) {
    unsigned long long r;
    asm("mov.b64 %0, {%1, %2};" : "=l"(r) : "f"(lo), "f"(hi));
    return r;
}
__device__ __forceinline__ void upk2(unsigned long long x, float& lo, float& hi) {
    asm("mov.b64 {%0, %1}, %2;" : "=f"(lo), "=f"(hi) : "l"(x));
}
__device__ __forceinline__ unsigned long long ffma2(unsigned long long a,
                                                    unsigned long long b,
                                                    unsigned long long c) {
    unsigned long long r;
    asm("fma.rn.f32x2 %0, %1, %2, %3;" : "=l"(r) : "l"(a), "l"(b), "l"(c));
    return r;
}

// ---------------- threefry2x32, key (0, 42), 20 rounds ----------------
__device__ __forceinline__ uint32_t threefry_bits(uint32_t idx) {
    uint32_t x0 = 0u, x1 = idx;
    const uint32_t ks0 = 0u;
    const uint32_t ks1 = 42u;
    const uint32_t ks2 = 0x1BD11BDAu ^ 42u;
    x0 += ks0;
    x1 += ks1;
#define TF_ROUND(r) { x0 += x1; x1 = __funnelshift_l(x1, x1, (r)); x1 ^= x0; }
    TF_ROUND(13) TF_ROUND(15) TF_ROUND(26) TF_ROUND(6)
    x0 += ks1; x1 += ks2 + 1u;
    TF_ROUND(17) TF_ROUND(29) TF_ROUND(16) TF_ROUND(24)
    x0 += ks2; x1 += ks0 + 2u;
    TF_ROUND(13) TF_ROUND(15) TF_ROUND(26) TF_ROUND(6)
    x0 += ks0; x1 += ks1 + 3u;
    TF_ROUND(17) TF_ROUND(29) TF_ROUND(16) TF_ROUND(24)
    x0 += ks1; x1 += ks2 + 4u;
    TF_ROUND(13) TF_ROUND(15) TF_ROUND(26) TF_ROUND(6)
    x0 += ks2; x1 += ks0 + 5u;
#undef TF_ROUND
    return x0 ^ x1;   // partitionable path: bits = out0 ^ out1
}

__global__ __launch_bounds__(256) void attn_dropout_kernel(
    const float* __restrict__ q,
    const float* __restrict__ k,
    const float* __restrict__ v,
    float* __restrict__ out)
{
    // P transpose buffer: Ps[warp][t*16 + s]
    __shared__ float Ps[8][256];

    const int warp = threadIdx.x >> 5;
    const int lane = threadIdx.x & 31;
    const int bh   = blockIdx.x * 8 + warp;

    const float* qb = q + (size_t)bh * 1024;
    const float* kb = k + (size_t)bh * 1024;
    const float* vb = v + (size_t)bh * 1024;

    // ================= Phase 1: scores (register-tiled 2s x 4t) =================
    // lane = sr*4 + tc; s in {sr, sr+8}; t in {tc, tc+4, tc+8, tc+12}
    const int sr = lane >> 2;
    const int tc = lane & 3;

    const float4* q0p = (const float4*)(qb + sr * 64);          // row sr
    const float4* q1p = (const float4*)(qb + (sr + 8) * 64);    // row sr+8
    const float4* k0p = (const float4*)(kb + tc * 64);          // row tc
    const float4* k1p = (const float4*)(kb + (tc + 4) * 64);
    const float4* k2p = (const float4*)(kb + (tc + 8) * 64);
    const float4* k3p = (const float4*)(kb + (tc + 12) * 64);

    unsigned long long acc[2][4];
    #pragma unroll
    for (int i = 0; i < 2; ++i)
        #pragma unroll
        for (int j = 0; j < 4; ++j)
            acc[i][j] = 0ull;   // (0.0f, 0.0f)

    #pragma unroll
    for (int c = 0; c < 16; ++c) {
        float4 qa = q0p[c];
        float4 qc = q1p[c];
        unsigned long long qa01 = pk2(qa.x, qa.y), qa23 = pk2(qa.z, qa.w);
        unsigned long long qc01 = pk2(qc.x, qc.y), qc23 = pk2(qc.z, qc.w);

        float4 kv;
        kv = k0p[c];
        { unsigned long long k01 = pk2(kv.x, kv.y), k23 = pk2(kv.z, kv.w);
          acc[0][0] = ffma2(qa01, k01, acc[0][0]); acc[0][0] = ffma2(qa23, k23, acc[0][0]);
          acc[1][0] = ffma2(qc01, k01, acc[1][0]); acc[1][0] = ffma2(qc23, k23, acc[1][0]); }
        kv = k1p[c];
        { unsigned long long k01 = pk2(kv.x, kv.y), k23 = pk2(kv.z, kv.w);
          acc[0][1] = ffma2(qa01, k01, acc[0][1]); acc[0][1] = ffma2(qa23, k23, acc[0][1]);
          acc[1][1] = ffma2(qc01, k01, acc[1][1]); acc[1][1] = ffma2(qc23, k23, acc[1][1]); }
        kv = k2p[c];
        { unsigned long long k01 = pk2(kv.x, kv.y), k23 = pk2(kv.z, kv.w);
          acc[0][2] = ffma2(qa01, k01, acc[0][2]); acc[0][2] = ffma2(qa23, k23, acc[0][2]);
          acc[1][2] = ffma2(qc01, k01, acc[1][2]); acc[1][2] = ffma2(qc23, k23, acc[1][2]); }
        kv = k3p[c];
        { unsigned long long k01 = pk2(kv.x, kv.y), k23 = pk2(kv.z, kv.w);
          acc[0][3] = ffma2(qa01, k01, acc[0][3]); acc[0][3] = ffma2(qa23, k23, acc[0][3]);
          acc[1][3] = ffma2(qc01, k01, acc[1][3]); acc[1][3] = ffma2(qc23, k23, acc[1][3]); }
    }

    // Horizontal combine + scale + mask(+1)
    float sc[2][4];
    #pragma unroll
    for (int i = 0; i < 2; ++i)
        #pragma unroll
        for (int j = 0; j < 4; ++j) {
            float lo, hi;
            upk2(acc[i][j], lo, hi);
            sc[i][j] = (lo + hi) * ATT_SCALE + 1.0f;
        }

    // ================= softmax over t (4 local + 2 shfl across tc-quad) =========
    #pragma unroll
    for (int i = 0; i < 2; ++i) {
        float m = fmaxf(fmaxf(sc[i][0], sc[i][1]), fmaxf(sc[i][2], sc[i][3]));
        m = fmaxf(m, __shfl_xor_sync(0xffffffffu, m, 1));
        m = fmaxf(m, __shfl_xor_sync(0xffffffffu, m, 2));
        float e0 = __expf(sc[i][0] - m);
        float e1 = __expf(sc[i][1] - m);
        float e2 = __expf(sc[i][2] - m);
        float e3 = __expf(sc[i][3] - m);
        float ssum = (e0 + e1) + (e2 + e3);
        ssum += __shfl_xor_sync(0xffffffffu, ssum, 1);
        ssum += __shfl_xor_sync(0xffffffffu, ssum, 2);
        // rs = (1/0.7)/sum : softmax normalization fused with dropout scale
        float rs = __fdividef(1.4285714285714286f, ssum);

        const int s = sr + 8 * i;
        const uint32_t base = (uint32_t)bh * 256u + (uint32_t)s * 16u + (uint32_t)tc;
        float e[4] = {e0, e1, e2, e3};
        #pragma unroll
        for (int j = 0; j < 4; ++j) {
            const int t = tc + 4 * j;
            uint32_t bits = threefry_bits(base + 4u * (uint32_t)j);
            float u = __uint_as_float((bits >> 9) | 0x3f800000u) - 1.0f;
            float p = (u < 0.7f) ? e[j] * rs : 0.0f;
            Ps[warp][t * 16 + s] = p;   // transposed store for PV phase
        }
    }
    __syncwarp();

    // ================= Phase 2: O = P @ V (lane = (s, half), interleaved d) =====
    // lane&15 = s row; lane>>4 = h. Lane owns d-chunks {2j+h}, j=0..7 (float4 units).
    const int s2 = lane & 15;
    const int h  = lane >> 4;
    const float4* vp = (const float4*)vb;

    unsigned long long oacc[16];
    #pragma unroll
    for (int j = 0; j < 16; ++j) oacc[j] = 0ull;

    const float* prow = &Ps[warp][s2];
    #pragma unroll
    for (int t = 0; t < 16; ++t) {
        float pv = prow[t * 16];                     // 16 distinct banks, 2-way dup
        unsigned long long p2 = pk2(pv, pv);
        #pragma unroll
        for (int j = 0; j < 8; ++j) {
            float4 vv = vp[t * 16 + 2 * j + h];      // 2 distinct adjacent f4, 16-dup
            oacc[2 * j]     = ffma2(p2, pk2(vv.x, vv.y), oacc[2 * j]);
            oacc[2 * j + 1] = ffma2(p2, pk2(vv.z, vv.w), oacc[2 * j + 1]);
        }
    }

    float4* op = (float4*)(out + (size_t)bh * 1024 + s2 * 64);
    #pragma unroll
    for (int j = 0; j < 8; ++j) {
        float x, y, z, w;
        upk2(oacc[2 * j], x, y);
        upk2(oacc[2 * j + 1], z, w);
        op[2 * j + h] = make_float4(x, y, z, w);
    }
}

extern "C" void kernel_launch(void* const* d_in, const int* in_sizes, int n_in,
                              void* d_out, int out_size) {
    const float* q = (const float*)d_in[0];
    const float* k = (const float*)d_in[1];
    const float* v = (const float*)d_in[2];
    float* out = (float*)d_out;
    attn_dropout_kernel<<<1024, 256>>>(q, k, v, out);
}